// round 13
// baseline (speedup 1.0000x reference)
#include <cuda_runtime.h>
#include <stdint.h>
#include <math.h>

#define NR   512
#define NO   64
#define NT   20
#define NS   300
#define NBUF 400
#define WIN  48
#define DT_F 0.0001f
#define UUB  500.0f

// fallback geometry
#define NCTA  32
#define TPB   512
#define NTH   (NCTA*TPB)
#define KPT   16
// cluster geometry
#define NCTA2 16
#define TPB2C 544            // 16 gather warps + 1 updater warp
#define NTH2  (NCTA2*512)    // gather-table threads (warps 0-15 only)
#define KPT2  32

// cluster smem layout (float units)
#define HIST_F  (2*WIN*NR)
#define SEI_F   HIST_F
#define SEI_B   (SEI_F*4)
#define SLED_F  (HIST_F + NR)        // sLEd[2][32] parity-buffered
#define SMEM_CLF (SLED_F + 64)
#define SMEM_CLB (SMEM_CLF*4)

__device__ float g_wl[NR*NR];
__device__ float g_rsum[NR];
__device__ float g_rssq[NR];
__device__ float g_dgd[NR];
__device__ float g_invnorm;
__device__ float g_pkw[KPT*NTH];   // cluster: 32*NTH2 == same size
__device__ int   g_pko[KPT*NTH];   // cluster: 16*NTH2 packed u16 pairs
__device__ float g_lmt[NO*NR];
__device__ float g_Mbuf[2][NR];
__device__ float g_EI[NR];
__device__ int   g_count;
__device__ int   g_ovf;

__device__ __forceinline__ int ld_acquire_gpu(const int* p) {
    int v;
    asm volatile("ld.global.acquire.gpu.b32 %0, [%1];" : "=r"(v) : "l"(p) : "memory");
    return v;
}
__device__ __forceinline__ void red_release_gpu(int* p, int v) {
    asm volatile("red.release.gpu.global.add.s32 [%0], %1;" :: "l"(p), "r"(v) : "memory");
}
__device__ __forceinline__ uint32_t smem_u32(const void* p) {
    uint32_t a;
    asm("{ .reg .u64 t; cvta.to.shared.u64 t, %1; cvt.u32.u64 %0, t; }" : "=r"(a) : "l"(p));
    return a;
}
__device__ __forceinline__ uint32_t mapa_u32(uint32_t laddr, uint32_t rank) {
    uint32_t r;
    asm("mapa.shared::cluster.u32 %0, %1, %2;" : "=r"(r) : "r"(laddr), "r"(rank));
    return r;
}
__device__ __forceinline__ void stc_f32(uint32_t raddr, float v) {
    asm volatile("st.shared::cluster.f32 [%0], %1;" :: "r"(raddr), "f"(v) : "memory");
}
#define CLUSTER_ARRIVE() asm volatile("barrier.cluster.arrive.aligned;" ::: "memory")
#define CLUSTER_WAIT()   asm volatile("barrier.cluster.wait.aligned;"   ::: "memory")

// ---------------- P1: w_l + row sums ----------------
__global__ void k_p1(const float* __restrict__ wbb, const float* __restrict__ sc)
{
    int i = blockIdx.x;
    int t = threadIdx.x;
    float a = expf(wbb[i*NR + t]) * sc[i*NR + t];
    float b = expf(wbb[t*NR + i]) * sc[t*NR + i];
    float wl = log1pf(0.5f * (a + b));
    g_wl[i*NR + t] = wl;

    float s1 = wl, s2 = wl * wl;
    #pragma unroll
    for (int off = 16; off; off >>= 1) {
        s1 += __shfl_down_sync(0xffffffffu, s1, off);
        s2 += __shfl_down_sync(0xffffffffu, s2, off);
    }
    __shared__ float sA[16], sB[16];
    int w = t >> 5, l = t & 31;
    if (l == 0) { sA[w] = s1; sB[w] = s2; }
    __syncthreads();
    if (w == 0) {
        float r1 = (l < 16) ? sA[l] : 0.f;
        float r2 = (l < 16) ? sB[l] : 0.f;
        #pragma unroll
        for (int off = 8; off; off >>= 1) {
            r1 += __shfl_down_sync(0xffffffffu, r1, off);
            r2 += __shfl_down_sync(0xffffffffu, r2, off);
        }
        if (l == 0) { g_rsum[i] = r1; g_rssq[i] = r2; }
    }
}

// ---------------- P2m: norm + dg + lm_t + flag reset ----------------
__global__ void k_p2m(const float* __restrict__ lm)
{
    int t = threadIdx.x;
    if (t == 0) { g_count = 0; g_ovf = 0; }

    float s2 = g_rssq[t];
    #pragma unroll
    for (int off = 16; off; off >>= 1) s2 += __shfl_down_sync(0xffffffffu, s2, off);
    __shared__ float sB[16];
    __shared__ float s_inv;
    int w = t >> 5, l = t & 31;
    if (l == 0) sB[w] = s2;
    __syncthreads();
    if (w == 0) {
        float r2 = (l < 16) ? sB[l] : 0.f;
        #pragma unroll
        for (int off = 8; off; off >>= 1) r2 += __shfl_down_sync(0xffffffffu, r2, off);
        if (l == 0) {
            float inv = 1.0f / sqrtf(r2);
            s_inv = inv;
            g_invnorm = inv;
        }
    }
    __syncthreads();
    g_dgd[t] = -s_inv * g_rsum[t];

    __shared__ float srs[NO];
    if (t < NO) {
        float s = 0.f;
        for (int i = 0; i < NR; i++) s += fabsf(lm[t*NR + i]);
        srs[t] = s;
    }
    __syncthreads();
    float cm = 0.f;
    for (int o = 0; o < NO; o++) cm += lm[o*NR + t] / srs[o];
    cm *= (1.0f / (float)NO);
    for (int o = 0; o < NO; o++) g_lmt[o*NR + t] = lm[o*NR + t] / srs[o] - cm;
}

// ---------------- P3a: fallback packing ----------------
__global__ void k_p3a(const float* __restrict__ dist, const float* __restrict__ theta)
{
    int id = blockIdx.x * TPB + threadIdx.x;
    int k   = id >> 14;
    int gt  = id & 16383;
    int c   = gt >> 9;
    int rem = gt & 511;
    int w2  = rem >> 5;
    int l   = rem & 31;
    int i   = c * 16 + w2;
    int j   = l + (k << 5);

    g_pkw[k*NTH + gt] = g_wl[i*NR + j] * g_invnorm;

    float denom = 1.5f + fmaxf(theta[16], 0.0f);
    int d = (int)(dist[j*NR + i] / denom);
    if (d < 0) d = 0;
    if (d > WIN - 1) d = WIN - 1;
    g_pko[k*NTH + gt] = ((WIN - d) * NR + j) * 4;
}

// ---------------- P3b: cluster packing, bank=lane, d==0-last sort ----------------
// lane l owns sources j ≡ l (mod 32). Warp w: region A=c*32+2w (slots 0..15),
// region B=c*32+2w+1 (slots 16..31). Per region: d>=1 first, d==0 in last <=6 slots.
__global__ void k_p3b(const float* __restrict__ dist, const float* __restrict__ theta)
{
    int gt = blockIdx.x * TPB + threadIdx.x;    // NTH2 threads
    int c   = gt >> 9;
    int rem = gt & 511;
    int w2  = rem >> 5;
    int l   = rem & 31;
    float denom = 1.5f + fmaxf(theta[16], 0.0f);

    unsigned packedO[16];
    for (int r = 0; r < 2; r++) {
        int i = c*32 + 2*w2 + r;
        float wE[16]; unsigned oE[16]; int ne = 0;
        float wL[6];  unsigned oL[6];  int nl = 0;
        for (int m = 0; m < 16; m++) {
            int j = l + 32*m;
            int d = (int)(dist[j*NR + i] / denom);
            if (d < 0) d = 0;
            if (d > WIN-1) d = WIN-1;
            float wgt = g_wl[i*NR + j] * g_invnorm;
            unsigned off = (unsigned)((WIN - d) * NR + j);
            if (d == 0 && nl < 6) { wL[nl] = wgt; oL[nl] = off; nl++; }
            else {
                if (d == 0) atomicExch(&g_ovf, 1);
                wE[ne] = wgt; oE[ne] = off; ne++;
            }
        }
        float ordW[16]; unsigned ordO[16];
        for (int t2 = 0; t2 < 16; t2++) {
            if (t2 < ne) { ordW[t2] = wE[t2]; ordO[t2] = oE[t2]; }
            else         { ordW[t2] = wL[t2-ne]; ordO[t2] = oL[t2-ne]; }
        }
        for (int t2 = 0; t2 < 16; t2++)
            g_pkw[(r*16 + t2)*NTH2 + gt] = ordW[t2];
        for (int kk = 0; kk < 8; kk++)
            packedO[r*8 + kk] = ordO[2*kk] | (ordO[2*kk+1] << 16);
    }
    for (int kk = 0; kk < 16; kk++)
        g_pko[kk*NTH2 + gt] = (int)packedO[kk];
}

__global__ void k_noop() {}

__device__ __forceinline__ void do_eeg(int o, int l, const float* sEI,
                                       float cy0, float y0_, float* out, int wnd)
{
    float sacc = 0.f;
    #pragma unroll
    for (int m2 = 0; m2 < 16; m2++) {
        int i2 = l + 32*m2;
        sacc = fmaf(__ldg(&g_lmt[o*NR + i2]), sEI[i2], sacc);
    }
    #pragma unroll
    for (int off = 16; off; off >>= 1)
        sacc += __shfl_down_sync(0xffffffffu, sacc, off);
    if (l == 0) out[o*NT + wnd] = cy0 * sacc - y0_;
}

// =========================================================================
// CLUSTER kernel: warp-specialized + barrier hidden under early (d>=1) gather
// =========================================================================
__global__ void __launch_bounds__(TPB2C, 1)
jr_cluster(const float* __restrict__ theta,
           const float* __restrict__ hx,
           const float* __restrict__ hE0,
           const float* __restrict__ ext,
           const float* __restrict__ noise,
           float* __restrict__ out)
{
    extern __shared__ float sm[];
    float* hist = sm;                    // [2*WIN][NR]
    float* sEI  = sm + SEI_F;            // [NR]
    float* sLEd = sm + SLED_F;           // [2][32]

    const int tid = threadIdx.x;
    const int c   = blockIdx.x;
    const int w   = tid >> 5;
    const int l   = tid & 31;
    const uint32_t sbase = smem_u32(sm);

    const float A_ = theta[0],  a_ = theta[1],  B_ = theta[2],  b_ = theta[3];
    const float gg = 0.01f + fmaxf(theta[4], 0.f);
    const float gf = 0.01f + fmaxf(theta[5], 0.f);
    const float gb = 0.01f + fmaxf(theta[6], 0.f);
    const float c1 = theta[7],  c2 = theta[8],  c3 = theta[9],  c4 = theta[10];
    const float rstd  = fmaxf(theta[11], 0.f);
    const float ncoef = 150.f + rstd;
    const float vmax = theta[12], v0 = theta[13], r_ = theta[14], y0_ = theta[15];
    const float ku   = (0.5f + fmaxf(theta[17], 0.f)) * theta[18];
    const float cy0  = theta[19];

    const int ovf = g_ovf;

    // gather warps: coupling tables
    float wk[KPT2]; unsigned okp[16];
    if (w < 16) {
        const int gt = c * 512 + tid;
        #pragma unroll
        for (int k = 0; k < KPT2; k++) wk[k] = g_pkw[k*NTH2 + gt];
        #pragma unroll
        for (int k = 0; k < 16; k++)  okp[k] = (unsigned)g_pko[k*NTH2 + gt];
    }

    // preload history
    for (int idx = tid; idx < WIN*NR; idx += TPB2C) {
        int q = idx >> 9;
        int j = idx & 511;
        int cc = (WIN - q) % WIN;
        float v = hE0[j*NBUF + cc];
        hist[q*NR + j]       = v;
        hist[(q+WIN)*NR + j] = v;
    }

    // updater warp: per-lane region state + scatter bases
    float M=0,E=0,I=0,Mv=0,Ev=0,Iv=0,dgd_i=0;
    float u_=0,n0=0,n1=0,n2=0;
    uint32_t rbl[16];
    const int i_reg = c*32 + l;
    if (w == 16) {
        M  = hx[i_reg*6 + 0]; E  = hx[i_reg*6 + 1]; I  = hx[i_reg*6 + 2];
        Mv = hx[i_reg*6 + 3]; Ev = hx[i_reg*6 + 4]; Iv = hx[i_reg*6 + 5];
        dgd_i = g_dgd[i_reg];
        #pragma unroll
        for (int k = 0; k < 16; k++)
            rbl[k] = mapa_u32(sbase, (uint32_t)k) + (uint32_t)i_reg * 4u;
        n0 = __ldg(noise + i_reg);
        n1 = __ldg(noise + NR + i_reg);
        n2 = __ldg(noise + 2*NR + i_reg);
        u_ = __ldg(ext + i_reg*(NS*NT));
    }

    __syncthreads();
    CLUSTER_ARRIVE();      // preloads visible everywhere
    CLUSTER_WAIT();
    CLUSTER_ARRIVE();      // priming arrive (first iteration's WAIT)

    int qq = 1;
    int pbase = 0;
    int pp = 0;

    for (int wnd = 0; wnd < NT; ++wnd) {
        for (int s = 0; s < NS; ++s) {
            float uu=0, nn0=0, nn1=0, nn2=0;
            float Mnext = 0.f;

            if (w < 16) {
                const float* hb = hist + pbase;
                float a0 = 0.f, a1 = 0.f, b0 = 0.f, b1 = 0.f;

                // ---- EARLY gather (d>=1; rows <= s-2, safe pre-WAIT) ----
                if (!ovf) {
                    #pragma unroll
                    for (int kk = 0; kk < 5; kk++) {        // region A terms 0..9
                        unsigned pk = okp[kk];
                        a0 = fmaf(wk[2*kk],   hb[pk & 0xFFFFu], a0);
                        a1 = fmaf(wk[2*kk+1], hb[pk >> 16],     a1);
                    }
                    #pragma unroll
                    for (int kk = 8; kk < 13; kk++) {       // region B terms 16..25
                        unsigned pk = okp[kk];
                        b0 = fmaf(wk[2*kk],   hb[pk & 0xFFFFu], b0);
                        b1 = fmaf(wk[2*kk+1], hb[pk >> 16],     b1);
                    }
                }

                CLUSTER_WAIT();   // phase s-1: row s-1 landed everywhere

                // EEG for previous window (EI scattered at (wnd,0), read at (wnd,1))
                if (s == 1 && wnd > 0 && w >= 4 && w < 8)
                    do_eeg(c*4 + (w - 4), l, sEI, cy0, y0_, out, wnd - 1);

                // ---- LATE gather ----
                if (!ovf) {
                    #pragma unroll
                    for (int kk = 5; kk < 8; kk++) {        // region A terms 10..15
                        unsigned pk = okp[kk];
                        a0 = fmaf(wk[2*kk],   hb[pk & 0xFFFFu], a0);
                        a1 = fmaf(wk[2*kk+1], hb[pk >> 16],     a1);
                    }
                    #pragma unroll
                    for (int kk = 13; kk < 16; kk++) {      // region B terms 26..31
                        unsigned pk = okp[kk];
                        b0 = fmaf(wk[2*kk],   hb[pk & 0xFFFFu], b0);
                        b1 = fmaf(wk[2*kk+1], hb[pk >> 16],     b1);
                    }
                } else {
                    #pragma unroll
                    for (int kk = 0; kk < 8; kk++) {
                        unsigned pk = okp[kk];
                        a0 = fmaf(wk[2*kk],   hb[pk & 0xFFFFu], a0);
                        a1 = fmaf(wk[2*kk+1], hb[pk >> 16],     a1);
                    }
                    #pragma unroll
                    for (int kk = 8; kk < 16; kk++) {
                        unsigned pk = okp[kk];
                        b0 = fmaf(wk[2*kk],   hb[pk & 0xFFFFu], b0);
                        b1 = fmaf(wk[2*kk+1], hb[pk >> 16],     b1);
                    }
                }
                float accA = a0 + a1, accB = b0 + b1;
                #pragma unroll
                for (int off = 16; off; off >>= 1) {
                    accA += __shfl_xor_sync(0xffffffffu, accA, off);
                    accB += __shfl_xor_sync(0xffffffffu, accB, off);
                }
                if (l == 0) {
                    sLEd[pp*32 + 2*w]     = accA;
                    sLEd[pp*32 + 2*w + 1] = accB;
                }
            } else {
                // ---- updater: scatter row s FIRST (no wait needed) ----
                Mnext = M + DT_F*Mv;
                const uint32_t qoff = (uint32_t)(qq*NR)*4u;
                #pragma unroll
                for (int k = 0; k < 16; k++) {
                    uint32_t ad = rbl[k] + qoff;
                    stc_f32(ad, Mnext);
                    stc_f32(ad + (uint32_t)(WIN*NR)*4u, Mnext);
                }
                if (s == 0 && wnd > 0) {
                    float EIv = E - I;   // end of previous window
                    #pragma unroll
                    for (int k = 0; k < 16; k++)
                        stc_f32(rbl[k] + (uint32_t)SEI_B, EIv);
                }
                // prefetch next iteration's inputs
                int sn = s + 1, wn = wnd;
                if (sn == NS) { sn = 0; wn = wnd + 1; if (wn == NT) { wn = NT-1; sn = NS-1; } }
                const float* nb = noise + (size_t)(wn*NS + sn) * 3 * NR + i_reg;
                nn0 = __ldg(nb); nn1 = __ldg(nb + NR); nn2 = __ldg(nb + 2*NR);
                uu  = __ldg(ext + i_reg*(NS*NT) + sn*NT + wn);

                CLUSTER_WAIT();   // phase s-1 (keeps phases matched)
            }

            __syncthreads();      // LEd published to sLEd[pp]
            CLUSTER_ARRIVE();     // release: covers updater's row-s scatter

            if (w == 16) {
                // ---- ODE update for region i_reg (32 lanes = 32 regions) ----
                float LEd = sLEd[pp*32 + l];
                float EmI = E - I;
                float S0 = vmax / (1.f + expf(r_ * (v0 - EmI)));
                float S1 = vmax / (1.f + expf(r_ * (v0 - c1*M)));
                float S2 = vmax / (1.f + expf(r_ * (v0 - c3*M)));
                float lmt_ = LEd + dgd_i * M;
                float let_ = LEd + dgd_i * EmI;
                float rM = ku*u_ + rstd*n0 + gg*lmt_ + S0;
                float rE = ncoef*n1 + gf*let_ + c2*S1;
                float rI = ncoef*n2 - gb*let_ + c4*S2;
                float En = E + DT_F*Ev;
                float In = I + DT_F*Iv;
                float uM = UUB * tanhf(rM * (1.f/UUB));
                float uE = UUB * tanhf(rE * (1.f/UUB));
                float uI = UUB * tanhf(rI * (1.f/UUB));
                float Mvn = Mv + DT_F*(A_*a_*uM - 2.f*a_*Mv - a_*a_*M);
                float Evn = Ev + DT_F*(A_*a_*uE - 2.f*a_*Ev - a_*a_*E);
                float Ivn = Iv + DT_F*(B_*b_*uI - 2.f*b_*Iv - b_*b_*I);
                M = Mnext; E = En; I = In; Mv = Mvn; Ev = Evn; Iv = Ivn;
                u_ = uu; n0 = nn0; n1 = nn1; n2 = nn2;
            }

            pbase = qq * NR;
            qq++; if (qq == WIN) qq = 0;
            pp ^= 1;
        }
    }

    // trailing: final window's EI + EEG
    if (w == 16) {
        float EIv = E - I;
        #pragma unroll
        for (int k = 0; k < 16; k++)
            stc_f32(rbl[k] + (uint32_t)SEI_B, EIv);
    }
    __syncthreads();
    CLUSTER_ARRIVE();
    CLUSTER_WAIT();
    if (w >= 4 && w < 8)
        do_eeg(c*4 + (w - 4), l, sEI, cy0, y0_, out, NT - 1);
}

// =========================================================================
// FALLBACK kernel (R2 design, 32 CTAs, L2 counter sync)
// =========================================================================
__global__ void __launch_bounds__(TPB, 1)
jr_main_fb(const float* __restrict__ theta,
           const float* __restrict__ hx,
           const float* __restrict__ hE0,
           const float* __restrict__ ext,
           const float* __restrict__ noise,
           float* __restrict__ out)
{
    extern __shared__ float sm[];
    float* hist  = sm;
    float* s_led = sm + 2*WIN*NR;

    const int tid = threadIdx.x;
    const int c   = blockIdx.x;
    const int w   = tid >> 5;
    const int l   = tid & 31;
    const int gt  = c * TPB + tid;

    float wk[KPT]; int ok[KPT];
    #pragma unroll
    for (int k = 0; k < KPT; k++) {
        wk[k] = g_pkw[k*NTH + gt];
        ok[k] = g_pko[k*NTH + gt];
    }

    for (int idx = tid; idx < WIN*NR; idx += TPB) {
        int q = idx >> 9;
        int j = idx & 511;
        int cc = (WIN - q) % WIN;
        float v = hE0[j*NBUF + cc];
        hist[q*NR + j]       = v;
        hist[(q+WIN)*NR + j] = v;
    }

    const float cy0 = theta[19];
    const float y0_ = theta[15];

    float M=0,E=0,I=0,Mv=0,Ev=0,Iv=0, dgd_i=0;
    float A_=0,a_=0,B_=0,b_=0,gg=0,gf=0,gb=0,c1=0,c2=0,c3=0,c4=0;
    float rstd=0,ncoef=0,vmax=0,v0=0,r_=0,ku=0;
    const int i_reg = c*16 + l;
    if (w == 0) {
        A_ = theta[0];  a_ = theta[1];  B_ = theta[2];  b_ = theta[3];
        gg = 0.01f + fmaxf(theta[4], 0.f);
        gf = 0.01f + fmaxf(theta[5], 0.f);
        gb = 0.01f + fmaxf(theta[6], 0.f);
        c1 = theta[7];  c2 = theta[8];  c3 = theta[9];  c4 = theta[10];
        rstd  = fmaxf(theta[11], 0.f);
        ncoef = 150.f + rstd;
        vmax = theta[12]; v0 = theta[13]; r_ = theta[14];
        ku   = (0.5f + fmaxf(theta[17], 0.f)) * theta[18];
        if (l < 16) {
            M  = hx[i_reg*6 + 0]; E  = hx[i_reg*6 + 1]; I  = hx[i_reg*6 + 2];
            Mv = hx[i_reg*6 + 3]; Ev = hx[i_reg*6 + 4]; Iv = hx[i_reg*6 + 5];
            dgd_i = g_dgd[i_reg];
        }
    }
    __syncthreads();

    int n = 1;
    int pbase = 0;

    for (int wnd = 0; wnd < NT; ++wnd) {
        for (int s = 0; s < NS; ++s) {
            float u_=0, n0=0, n1=0, n2=0;
            if (w == 0 && l < 16) {
                int t_lin = wnd*NS + s;
                const float* nb = noise + (size_t)t_lin * 3 * NR + i_reg;
                n0 = __ldg(nb); n1 = __ldg(nb + NR); n2 = __ldg(nb + 2*NR);
                u_ = __ldg(ext + i_reg*(NS*NT) + s*NT + wnd);
            }

            const char* hrow = (const char*)(hist + pbase);
            float acc0 = 0.f, acc1 = 0.f;
            #pragma unroll
            for (int k = 0; k < KPT; k += 2) {
                acc0 = fmaf(wk[k],   *(const float*)(hrow + ok[k]),   acc0);
                acc1 = fmaf(wk[k+1], *(const float*)(hrow + ok[k+1]), acc1);
            }
            float acc = acc0 + acc1;
            #pragma unroll
            for (int off = 16; off; off >>= 1)
                acc += __shfl_down_sync(0xffffffffu, acc, off);
            if (l == 0) s_led[w] = acc;
            __syncthreads();

            const int par = n & 1;

            if (w == 0) {
                if (l < 16) {
                    float LEd = s_led[l];
                    float EmI = E - I;
                    float S0 = vmax / (1.f + expf(r_ * (v0 - EmI)));
                    float S1 = vmax / (1.f + expf(r_ * (v0 - c1*M)));
                    float S2 = vmax / (1.f + expf(r_ * (v0 - c3*M)));
                    float lmt_ = LEd + dgd_i * M;
                    float let_ = LEd + dgd_i * EmI;
                    float rM = ku*u_ + rstd*n0 + gg*lmt_ + S0;
                    float rE = ncoef*n1 + gf*let_ + c2*S1;
                    float rI = ncoef*n2 - gb*let_ + c4*S2;
                    float Mn = M + DT_F*Mv;
                    float En = E + DT_F*Ev;
                    float In = I + DT_F*Iv;
                    float uM = UUB * tanhf(rM * (1.f/UUB));
                    float uE = UUB * tanhf(rE * (1.f/UUB));
                    float uI = UUB * tanhf(rI * (1.f/UUB));
                    float Mvn = Mv + DT_F*(A_*a_*uM - 2.f*a_*Mv - a_*a_*M);
                    float Evn = Ev + DT_F*(A_*a_*uE - 2.f*a_*Ev - a_*a_*E);
                    float Ivn = Iv + DT_F*(B_*b_*uI - 2.f*b_*Iv - b_*b_*I);
                    M = Mn; E = En; I = In; Mv = Mvn; Ev = Evn; Iv = Ivn;
                    __stcg(&g_Mbuf[par][i_reg], M);
                    if (s == NS-1) __stcg(&g_EI[i_reg], E - I);
                }
                __threadfence();
                if (l == 0) {
                    red_release_gpu(&g_count, 1);
                    const int target = NCTA * n;
                    while (ld_acquire_gpu(&g_count) < target) { }
                }
            }
            __syncthreads();

            {
                float v = __ldcg(&g_Mbuf[par][tid]);
                int q = n % WIN;
                hist[q*NR + tid]       = v;
                hist[(q+WIN)*NR + tid] = v;
            }

            if (s == NS-1 && (w == 8 || w == 9)) {
                int o = 2*c + (w - 8);
                float sacc = 0.f;
                #pragma unroll
                for (int m = 0; m < 16; m++) {
                    int i2 = l + 32*m;
                    sacc = fmaf(__ldg(&g_lmt[o*NR + i2]), __ldcg(&g_EI[i2]), sacc);
                }
                #pragma unroll
                for (int off = 16; off; off >>= 1)
                    sacc += __shfl_down_sync(0xffffffffu, sacc, off);
                if (l == 0) out[o*NT + wnd] = cy0 * sacc - y0_;
            }

            __syncthreads();
            pbase = (n % WIN) * NR;
            n++;
        }
    }
}

extern "C" void kernel_launch(void* const* d_in, const int* in_sizes, int n_in,
                              void* d_out, int out_size)
{
    const float* theta = (const float*)d_in[0];
    const float* lm    = (const float*)d_in[1];
    const float* wbb   = (const float*)d_in[2];
    const float* sc    = (const float*)d_in[3];
    const float* dist  = (const float*)d_in[4];
    const float* hx    = (const float*)d_in[5];
    const float* hE0   = (const float*)d_in[6];
    const float* ext   = (const float*)d_in[7];
    const float* noise = (const float*)d_in[8];
    float* out = (float*)d_out;

    (void)in_sizes; (void)n_in; (void)out_size;

    const size_t SMEM_FB = (size_t)(2*WIN*NR + 32) * sizeof(float);
    const size_t SMEM_CL = (size_t)SMEM_CLB;

    cudaFuncSetAttribute(jr_main_fb, cudaFuncAttributeMaxDynamicSharedMemorySize, (int)SMEM_FB);
    cudaError_t e1 = cudaFuncSetAttribute(jr_cluster, cudaFuncAttributeNonPortableClusterSizeAllowed, 1);
    cudaError_t e2 = cudaFuncSetAttribute(jr_cluster, cudaFuncAttributeMaxDynamicSharedMemorySize, (int)SMEM_CL);

    cudaLaunchConfig_t cfg = {};
    cfg.gridDim  = dim3(NCTA2, 1, 1);
    cfg.blockDim = dim3(TPB2C, 1, 1);
    cfg.dynamicSmemBytes = SMEM_CL;
    cfg.stream = 0;
    cudaLaunchAttribute at[1];
    at[0].id = cudaLaunchAttributeClusterDimension;
    at[0].val.clusterDim.x = NCTA2;
    at[0].val.clusterDim.y = 1;
    at[0].val.clusterDim.z = 1;
    cfg.attrs = at;
    cfg.numAttrs = 1;

    int ncl = 0;
    cudaError_t qe = cudaOccupancyMaxActiveClusters(&ncl, jr_cluster, &cfg);
    bool use_cluster = (e1 == cudaSuccess) && (e2 == cudaSuccess) &&
                       (qe == cudaSuccess) && (ncl >= 1);

    k_p1<<<NR, TPB>>>(wbb, sc);
    k_p2m<<<1, TPB>>>(lm);

    if (use_cluster) {
        k_p3b<<<NCTA2, TPB>>>(dist, theta);
        cudaLaunchKernelEx(&cfg, jr_cluster, theta, hx, hE0, ext, noise, out);
    } else {
        k_p3a<<<(KPT*NTH)/TPB, TPB>>>(dist, theta);
        jr_main_fb<<<NCTA, TPB, SMEM_FB>>>(theta, hx, hE0, ext, noise, out);
    }
    k_noop<<<1, 32>>>();
}